// round 8
// baseline (speedup 1.0000x reference)
#include <cuda_runtime.h>
#include <cuda_bf16.h>
#include <cstdint>

#define DD    784
#define CC    10
#define NTOT  7840
#define NBC   64
#define NBLK  123
#define GRIDM (NBLK * 2)
#define NCHT  13
#define PITCH 144

#define TA_SZ 36864
#define OFF_TA0 0
#define OFF_TA1 36864
#define OFF_TB0 73728
#define OFF_TB1 92160
#define OFF_MBAR 110592
#define SMEM_TOTAL 110656
#define OFF_BNC 0            // bounce aliases TA0 after mainloop

__device__ __align__(16) unsigned char g_A[NCHT * TA_SZ];
__device__ float g_part[GRIDM * 2 * CC * 128];   // [slice][c][b]

__device__ __forceinline__ uint32_t smem_u32(const void* p) {
    uint32_t a;
    asm("{ .reg .u64 t; cvta.to.shared.u64 t, %1; cvt.u32.u64 %0, t; }" : "=r"(a) : "l"(p));
    return a;
}
#define MBAR_INIT(a, n) asm volatile("mbarrier.init.shared.b64 [%0], %1;" :: "r"(a), "r"(n) : "memory")
#define MBAR_EXPECT(a, n) asm volatile("mbarrier.arrive.expect_tx.shared.b64 _, [%0], %1;" :: "r"(a), "r"(n) : "memory")
#define MBAR_WAIT(a, ph) do {                                                   \
    asm volatile("{ .reg .pred P1; WL%=:"                                       \
        " mbarrier.try_wait.parity.acquire.cta.shared::cta.b64 P1, [%0], %1, 0x989680;" \
        " @P1 bra.uni WD%=; bra.uni WL%=; WD%=: }"                              \
        :: "r"(a), "r"(ph) : "memory");                                         \
} while (0)
#define BULK(dst, src, sz, mb) \
    asm volatile("cp.async.bulk.shared::cluster.global.mbarrier::complete_tx::bytes " \
        "[%0], [%1], %2, [%3];" :: "r"(dst), "l"(src), "r"(sz), "r"(mb) : "memory")
#define LDSM4(r, addr) \
    asm volatile("ldmatrix.sync.aligned.m8n8.x4.shared.b16 {%0,%1,%2,%3}, [%4];" \
        : "=r"((r)[0]), "=r"((r)[1]), "=r"((r)[2]), "=r"((r)[3]) : "r"(addr))
#define MMA_BF16(d, a, br0, br1) \
    asm volatile("mma.sync.aligned.m16n8k16.row.col.f32.bf16.bf16.f32 " \
        "{%0,%1,%2,%3}, {%4,%5,%6,%7}, {%8,%9}, {%0,%1,%2,%3};" \
        : "+f"((d)[0]), "+f"((d)[1]), "+f"((d)[2]), "+f"((d)[3]) \
        : "r"((a)[0]), "r"((a)[1]), "r"((a)[2]), "r"((a)[3]), "r"(br0), "r"(br1))

// ---------- prep: X -> bf16 hi/lo padded tile image per k-chunk ----------
__global__ __launch_bounds__(256)
void prep_a(const float* __restrict__ X) {
    int flat = blockIdx.x * 256 + threadIdx.x;   // 13*128*16 = 26624
    int ch  = flat >> 11;
    int rem = flat & 2047;
    int b   = rem >> 4;
    int k   = (rem & 15) * 4;
    int j   = ch * 64 + k;
    float f[4] = {0.f, 0.f, 0.f, 0.f};
    if (j < DD) {
        float4 v = *(const float4*)(X + b * DD + j);
        f[0] = v.x; f[1] = v.y; f[2] = v.z; f[3] = v.w;
    }
    __nv_bfloat16 h[4], l[4];
#pragma unroll
    for (int e = 0; e < 4; e++) {
        h[e] = __float2bfloat16(f[e]);
        l[e] = __float2bfloat16(f[e] - __bfloat162float(h[e]));
    }
    unsigned char* base = g_A + ch * TA_SZ + b * PITCH + k * 2;
    *(uint2*)(base)         = *(uint2*)h;
    *(uint2*)(base + 18432) = *(uint2*)l;
}

// ---------- main ----------
__global__ __launch_bounds__(256, 2)
void mma_main(const float* __restrict__ X, const float* __restrict__ W) {
    extern __shared__ __align__(16) unsigned char smem[];
    const uint32_t sb = smem_u32(smem);
    const int tid = threadIdx.x, lane = tid & 31, wid = tid >> 5;
    const int bx = blockIdx.x;
    const int nb_idx = bx >> 1, kb = bx & 1;
    const int n0 = nb_idx * NBC;
    const int NCH = kb ? 6 : 7;       // kb0: chunks 0..6, kb1: 7..12
    const int gch0 = kb ? 7 : 0;

    const int wm = wid >> 1, wn = wid & 1;
    const int m_base = wm * 32, n_base = wn * 32;
    const int rsel = (lane & 7) + ((lane >> 3) & 1) * 8;
    const int k8b  = ((lane >> 4) * 8) * 2;
    int aoff[2], boff[2];
#pragma unroll
    for (int q = 0; q < 2; q++) {
        aoff[q] = (m_base + q * 16 + rsel) * PITCH + k8b;
        boff[q] = (n_base + q * 16 + rsel) * PITCH + k8b;
    }

    float acc[2][4][4];
#pragma unroll
    for (int a = 0; a < 2; a++)
#pragma unroll
        for (int b = 0; b < 4; b++)
#pragma unroll
            for (int e = 0; e < 4; e++) acc[a][b][e] = 0.f;

    if (tid == 0) { MBAR_INIT(sb + OFF_MBAR, 1); MBAR_INIT(sb + OFF_MBAR + 8, 1); }
    __syncthreads();

    auto issueA = [&](int ch) {
        if (tid == 0) {
            const int buf = ch & 1;
            const uint32_t mb = sb + OFF_MBAR + buf * 8;
            MBAR_EXPECT(mb, TA_SZ);
            BULK(sb + (buf ? OFF_TA1 : OFF_TA0), g_A + (gch0 + ch) * TA_SZ, TA_SZ, mb);
        }
    };

    // per-thread B plan: n = (tid&63), kp0 = tid>>6 covers k = 2*(kp0 + 4r)
    const int nloc = tid & 63;
    const int kp0  = tid >> 6;                    // 0..3
    const int ng   = n0 + nloc;
    const bool nok = (ng < NTOT);
    const int i_g  = nok ? (ng / 10) : 0;
    const int c_g  = nok ? (ng - i_g * 10) : 0;
    const float* wbase = W + ((size_t)(i_g + 1) * DD) * 10 + c_g;

    float rB[16];
    auto loadB = [&](int ch) {
        const int j0 = (gch0 + ch) * 64;
#pragma unroll
        for (int r = 0; r < 8; r++) {
            int k = (kp0 + r * 4) * 2;
            int j = j0 + k;
            bool ok = nok && (j < DD);
            rB[r * 2]     = ok ? wbase[(size_t)j * 10] : 0.f;
            rB[r * 2 + 1] = (nok && (j + 1 < DD)) ? wbase[(size_t)(j + 1) * 10] : 0.f;
        }
    };
    auto storeB = [&](int buf) {
        unsigned char* tb = smem + (buf ? OFF_TB1 : OFF_TB0);
#pragma unroll
        for (int r = 0; r < 8; r++) {
            int k = (kp0 + r * 4) * 2;
            float v0 = rB[r * 2], v1 = rB[r * 2 + 1];
            __nv_bfloat162 hp, lp;
            hp.x = __float2bfloat16(v0);
            hp.y = __float2bfloat16(v1);
            lp.x = __float2bfloat16(v0 - __bfloat162float(hp.x));
            lp.y = __float2bfloat16(v1 - __bfloat162float(hp.y));
            *(__nv_bfloat162*)(tb + nloc * PITCH + k * 2)        = hp;
            *(__nv_bfloat162*)(tb + 9216 + nloc * PITCH + k * 2) = lp;
        }
    };

    // prologue: A depth-2 prefetch, B chunk 0 in flight
    issueA(0);
    if (NCH > 1) issueA(1);
    loadB(0);

    for (int ch = 0; ch < NCH; ch++) {
        const int buf = ch & 1;
        storeB(buf);                       // TB[buf] free (MMA(ch-2) synced)
        __syncthreads();                   // TB visible to all warps
        if (ch + 1 < NCH) loadB(ch + 1);   // LDGs overlap wait + MMA
        MBAR_WAIT(sb + OFF_MBAR + buf * 8, (ch >> 1) & 1);

        const uint32_t tA = sb + (buf ? OFF_TA1 : OFF_TA0);
        const uint32_t tB = sb + (buf ? OFF_TB1 : OFF_TB0);
#pragma unroll
        for (int s = 0; s < 4; s++) {
            const int koff = s * 32;
            uint32_t ah[2][4], al[2][4], bh[2][4], bl[2][4];
#pragma unroll
            for (int q = 0; q < 2; q++) {
                LDSM4(ah[q], tA + aoff[q] + koff);
                LDSM4(al[q], tA + 18432 + aoff[q] + koff);
                LDSM4(bh[q], tB + boff[q] + koff);
                LDSM4(bl[q], tB + 9216 + boff[q] + koff);
            }
#pragma unroll
            for (int mi = 0; mi < 2; mi++)
#pragma unroll
                for (int j = 0; j < 4; j++) {
                    const int nt = j >> 1, pr = j & 1;
                    MMA_BF16(acc[mi][j], ah[mi], bh[nt][pr], bh[nt][pr + 2]);
                    MMA_BF16(acc[mi][j], ah[mi], bl[nt][pr], bl[nt][pr + 2]);
                    MMA_BF16(acc[mi][j], al[mi], bh[nt][pr], bh[nt][pr + 2]);
                }
        }
        __syncthreads();                   // all warps done with TA[buf], TB[buf]
        if (ch + 2 < NCH) issueA(ch + 2);
    }

    // ---- epilogue ----
    float* bnc = (float*)(smem + OFF_BNC);       // [128][66], aliases TA0
    {
        const int r = lane >> 2, cq = (lane & 3) * 2;
#pragma unroll
        for (int mi = 0; mi < 2; mi++)
#pragma unroll
            for (int j = 0; j < 4; j++) {
                int row = m_base + mi * 16 + r;
                int col = n_base + j * 8 + cq;
                *(float2*)(bnc + row * 66 + col)       = make_float2(acc[mi][j][0], acc[mi][j][1]);
                *(float2*)(bnc + (row + 8) * 66 + col) = make_float2(acc[mi][j][2], acc[mi][j][3]);
            }
    }
    __syncthreads();
    {
        const int b = tid >> 1, half = tid & 1;
        const int nw = n0 + half * 32;
        const int i_b = nw / 10, r0 = nw - i_b * 10;
        float tacc[10];
#pragma unroll
        for (int k = 0; k < 10; k++) tacc[k] = 0.f;
#pragma unroll
        for (int nl = 0; nl < 32; nl++) {
            int n = nw + nl;
            if (n < NTOT) {
                int idx = r0 + nl;
                int add = (idx >= 10) + (idx >= 20) + (idx >= 30) + (idx >= 40);
                float xv = X[b * DD + i_b + add];
                float w1 = (kb == 0) ? W[n] : 0.f;
                float g  = bnc[b * 66 + half * 32 + nl];
                tacc[nl % 10] += xv * (g + w1);
            }
        }
        float* seg = g_part + (bx * 2 + half) * (CC * 128);
#pragma unroll
        for (int k = 0; k < 10; k++) {
            int c = r0 + k; if (c >= 10) c -= 10;
            seg[c * 128 + b] = tacc[k];
        }
    }
}

// ---------- reduce: grid 10, block 512 = 4 kseg x 128 b ----------
__global__ __launch_bounds__(512)
void reduce_k(const float* __restrict__ bias, float* __restrict__ out) {
    __shared__ float sm[512];
    const int c = blockIdx.x, t = threadIdx.x;
    const int b = t & 127, sg = t >> 7;
    const int NS = GRIDM * 2;                    // 492 slices
    float s = 0.f;
    for (int q = sg; q < NS; q += 4)
        s += g_part[q * (CC * 128) + c * 128 + b];
    sm[t] = s;
    __syncthreads();
    if (sg == 0)
        out[b * 10 + c] = sm[b] + sm[128 + b] + sm[256 + b] + sm[384 + b] + bias[c];
}

extern "C" void kernel_launch(void* const* d_in, const int* in_sizes, int n_in,
                              void* d_out, int out_size) {
    const float* X    = (const float*)d_in[0];
    const float* W    = (const float*)d_in[1];
    const float* bias = (const float*)d_in[2];
    float* out        = (float*)d_out;
    (void)in_sizes; (void)n_in; (void)out_size;

    cudaFuncSetAttribute(mma_main, cudaFuncAttributeMaxDynamicSharedMemorySize, SMEM_TOTAL);
    prep_a<<<104, 256>>>(X);
    mma_main<<<GRIDM, 256, SMEM_TOTAL>>>(X, W);
    reduce_k<<<CC, 512>>>(bias, out);
}

// round 10
// speedup vs baseline: 1.2742x; 1.2742x over previous
#include <cuda_runtime.h>
#include <cuda_bf16.h>
#include <cstdint>

#define DD    784
#define CC    10
#define NTOT  7840
#define NBC   112
#define GRIDM 140
#define NCHT  13
#define PITCH 144

#define TA_SZ   36864          // [2 split][128][72] bf16
#define OFF_TA0 0
#define OFF_TA1 36864
#define OFF_TB0 73728          // [2 split][128 rows][72] bf16 (rows 112-127 zero)
#define OFF_TB1 110592
#define OFF_MBAR 147456
#define SMEM_TOTAL 147520
#define OFF_BNC 0              // bounce aliases TA after mainloop

__device__ __align__(16) unsigned char g_A[NCHT * TA_SZ];
__device__ float g_part[GRIDM * 2 * CC * 128];   // [slice][c][b]

__device__ __forceinline__ uint32_t smem_u32(const void* p) {
    uint32_t a;
    asm("{ .reg .u64 t; cvta.to.shared.u64 t, %1; cvt.u32.u64 %0, t; }" : "=r"(a) : "l"(p));
    return a;
}
#define MBAR_INIT(a, n) asm volatile("mbarrier.init.shared.b64 [%0], %1;" :: "r"(a), "r"(n) : "memory")
#define MBAR_EXPECT(a, n) asm volatile("mbarrier.arrive.expect_tx.shared.b64 _, [%0], %1;" :: "r"(a), "r"(n) : "memory")
#define MBAR_WAIT(a, ph) do {                                                   \
    asm volatile("{ .reg .pred P1; WL%=:"                                       \
        " mbarrier.try_wait.parity.acquire.cta.shared::cta.b64 P1, [%0], %1, 0x989680;" \
        " @P1 bra.uni WD%=; bra.uni WL%=; WD%=: }"                              \
        :: "r"(a), "r"(ph) : "memory");                                         \
} while (0)
#define BULK(dst, src, sz, mb) \
    asm volatile("cp.async.bulk.shared::cluster.global.mbarrier::complete_tx::bytes " \
        "[%0], [%1], %2, [%3];" :: "r"(dst), "l"(src), "r"(sz), "r"(mb) : "memory")
#define LDSM4(r, addr) \
    asm volatile("ldmatrix.sync.aligned.m8n8.x4.shared.b16 {%0,%1,%2,%3}, [%4];" \
        : "=r"((r)[0]), "=r"((r)[1]), "=r"((r)[2]), "=r"((r)[3]) : "r"(addr))
#define MMA_BF16(d, a, br0, br1) \
    asm volatile("mma.sync.aligned.m16n8k16.row.col.f32.bf16.bf16.f32 " \
        "{%0,%1,%2,%3}, {%4,%5,%6,%7}, {%8,%9}, {%0,%1,%2,%3};" \
        : "+f"((d)[0]), "+f"((d)[1]), "+f"((d)[2]), "+f"((d)[3]) \
        : "r"((a)[0]), "r"((a)[1]), "r"((a)[2]), "r"((a)[3]), "r"(br0), "r"(br1))

// ---------- prep: X -> bf16 hi/lo padded tile image per k-chunk ----------
__global__ __launch_bounds__(128)
void prep_a(const float* __restrict__ X) {
    int flat = blockIdx.x * 128 + threadIdx.x;   // 13*128*16 = 26624
    int ch  = flat >> 11;
    int rem = flat & 2047;
    int b   = rem >> 4;
    int k   = (rem & 15) * 4;
    int j   = ch * 64 + k;
    float f[4] = {0.f, 0.f, 0.f, 0.f};
    if (j < DD) {
        float4 v = *(const float4*)(X + b * DD + j);
        f[0] = v.x; f[1] = v.y; f[2] = v.z; f[3] = v.w;
    }
    __nv_bfloat16 h[4], l[4];
#pragma unroll
    for (int e = 0; e < 4; e++) {
        h[e] = __float2bfloat16(f[e]);
        l[e] = __float2bfloat16(f[e] - __bfloat162float(h[e]));
    }
    unsigned char* base = g_A + ch * TA_SZ + b * PITCH + k * 2;
    *(uint2*)(base)         = *(uint2*)h;
    *(uint2*)(base + 18432) = *(uint2*)l;
}

// ---------- main ----------
__global__ __launch_bounds__(256, 1)
void mma_main(const float* __restrict__ X, const float* __restrict__ W) {
    extern __shared__ __align__(16) unsigned char smem[];
    const uint32_t sb = smem_u32(smem);
    const int tid = threadIdx.x, lane = tid & 31, wid = tid >> 5;
    const int bx = blockIdx.x;
    const int nb_idx = bx >> 1, kb = bx & 1;
    const int n0 = nb_idx * NBC;
    const int NCH = kb ? 6 : 7;       // kb0: chunks 0..6, kb1: 7..12
    const int gch0 = kb ? 7 : 0;

    const int wm = wid >> 1, wn = wid & 1;
    const int m_base = wm * 32, n_base = wn * 56;
    const int rsel = (lane & 7) + ((lane >> 3) & 1) * 8;
    const int k8b  = ((lane >> 4) * 8) * 2;
    int aoff[2], boff[4];
#pragma unroll
    for (int q = 0; q < 2; q++) aoff[q] = (m_base + q * 16 + rsel) * PITCH + k8b;
#pragma unroll
    for (int q = 0; q < 4; q++) boff[q] = (n_base + q * 16 + rsel) * PITCH + k8b;

    float acc[2][7][4];
#pragma unroll
    for (int a = 0; a < 2; a++)
#pragma unroll
        for (int t = 0; t < 7; t++)
#pragma unroll
            for (int e = 0; e < 4; e++) acc[a][t][e] = 0.f;

    // zero pad rows 112..127 of both TB buffers / both splits (4 regions x 576 words)
    for (int u = tid; u < 2304; u += 256) {
        int p = u / 576, off = u - p * 576;
        int base = OFF_TB0 + (p >> 1) * (OFF_TB1 - OFF_TB0) + (p & 1) * 18432;
        *(uint32_t*)(smem + base + 112 * PITCH + off * 4) = 0;
    }
    if (tid == 0) { MBAR_INIT(sb + OFF_MBAR, 1); MBAR_INIT(sb + OFF_MBAR + 8, 1); }
    __syncthreads();

    auto issueA = [&](int ch) {
        if (tid == 0) {
            const int buf = ch & 1;
            const uint32_t mb = sb + OFF_MBAR + buf * 8;
            MBAR_EXPECT(mb, TA_SZ);
            BULK(sb + (buf ? OFF_TA1 : OFF_TA0), g_A + (gch0 + ch) * TA_SZ, TA_SZ, mb);
        }
    };

    // B plan: 224 active threads; thread -> (nloc 0..111, kp0 0..1); 16 k-pairs each
    const bool bact = tid < 224;
    const int kp0  = (tid >= 112) ? 1 : 0;
    const int nloc = bact ? (tid - kp0 * 112) : 0;
    const int ng   = n0 + nloc;
    const int i_g  = ng / 10;
    const int c_g  = ng - i_g * 10;
    const float* wbase = W + (size_t)(i_g + 1) * NTOT + c_g;

    float2 rB[16];
    auto loadB = [&](int ch) {
        if (!bact) return;
        const int j0 = (gch0 + ch) * 64 + kp0 * 2;
#pragma unroll
        for (int r = 0; r < 16; r++) {
            int j = j0 + r * 4;
            rB[r].x = (j < DD)     ? wbase[(size_t)j * 10]       : 0.f;
            rB[r].y = (j + 1 < DD) ? wbase[(size_t)(j + 1) * 10] : 0.f;
        }
    };
    auto storeB = [&](int buf) {
        if (!bact) return;
        unsigned char* tb = smem + (buf ? OFF_TB1 : OFF_TB0) + nloc * PITCH + kp0 * 4;
#pragma unroll
        for (int r = 0; r < 16; r++) {
            float v0 = rB[r].x, v1 = rB[r].y;
            __nv_bfloat162 hp, lp;
            hp.x = __float2bfloat16(v0);
            hp.y = __float2bfloat16(v1);
            lp.x = __float2bfloat16(v0 - __bfloat162float(hp.x));
            lp.y = __float2bfloat16(v1 - __bfloat162float(hp.y));
            *(__nv_bfloat162*)(tb + r * 8)         = hp;
            *(__nv_bfloat162*)(tb + 18432 + r * 8) = lp;
        }
    };

    issueA(0);
    if (NCH > 1) issueA(1);
    loadB(0);

    for (int ch = 0; ch < NCH; ch++) {
        const int buf = ch & 1;
        storeB(buf);
        __syncthreads();
        if (ch + 1 < NCH) loadB(ch + 1);
        MBAR_WAIT(sb + OFF_MBAR + buf * 8, (ch >> 1) & 1);

        const uint32_t tA = sb + (buf ? OFF_TA1 : OFF_TA0);
        const uint32_t tB = sb + (buf ? OFF_TB1 : OFF_TB0);
#pragma unroll
        for (int s = 0; s < 4; s++) {
            const int koff = s * 32;
            uint32_t ah[2][4], al[2][4], bb[4][4];
#pragma unroll
            for (int q = 0; q < 2; q++) {
                LDSM4(ah[q], tA + aoff[q] + koff);
                LDSM4(al[q], tA + 18432 + aoff[q] + koff);
            }
#pragma unroll
            for (int q = 0; q < 4; q++) LDSM4(bb[q], tB + boff[q] + koff);
#pragma unroll
            for (int mi = 0; mi < 2; mi++)
#pragma unroll
                for (int nt = 0; nt < 7; nt++) {
                    MMA_BF16(acc[mi][nt], ah[mi], bb[nt >> 1][nt & 1], bb[nt >> 1][(nt & 1) + 2]);
                    MMA_BF16(acc[mi][nt], al[mi], bb[nt >> 1][nt & 1], bb[nt >> 1][(nt & 1) + 2]);
                }
#pragma unroll
            for (int q = 0; q < 4; q++) LDSM4(bb[q], tB + 18432 + boff[q] + koff);
#pragma unroll
            for (int mi = 0; mi < 2; mi++)
#pragma unroll
                for (int nt = 0; nt < 7; nt++)
                    MMA_BF16(acc[mi][nt], ah[mi], bb[nt >> 1][nt & 1], bb[nt >> 1][(nt & 1) + 2]);
        }
        __syncthreads();
        if (ch + 2 < NCH) issueA(ch + 2);
    }

    // ---- epilogue ----
    float* bnc = (float*)(smem + OFF_BNC);       // [128][114], aliases TA
    {
        const int r = lane >> 2, cq = (lane & 3) * 2;
#pragma unroll
        for (int mi = 0; mi < 2; mi++)
#pragma unroll
            for (int nt = 0; nt < 7; nt++) {
                int row = m_base + mi * 16 + r;
                int col = n_base + nt * 8 + cq;
                *(float2*)(bnc + row * 114 + col)       = make_float2(acc[mi][nt][0], acc[mi][nt][1]);
                *(float2*)(bnc + (row + 8) * 114 + col) = make_float2(acc[mi][nt][2], acc[mi][nt][3]);
            }
    }
    __syncthreads();
    {
        const int b = tid >> 1, half = tid & 1;
        const int nw = n0 + half * 56;
        const int i_b = nw / 10, r0 = nw - i_b * 10;
        float tacc[10];
#pragma unroll
        for (int k = 0; k < 10; k++) tacc[k] = 0.f;
#pragma unroll
        for (int nl = 0; nl < 56; nl++) {
            int idx = r0 + nl;
            int add = (idx >= 10) + (idx >= 20) + (idx >= 30) +
                      (idx >= 40) + (idx >= 50) + (idx >= 60);
            float xv = X[b * DD + i_b + add];
            float w1 = (kb == 0) ? W[nw + nl] : 0.f;
            float g  = bnc[b * 114 + half * 56 + nl];
            tacc[nl % 10] += xv * (g + w1);
        }
        float* seg = g_part + (bx * 2 + half) * (CC * 128);
#pragma unroll
        for (int k = 0; k < 10; k++) {
            int c = r0 + k; if (c >= 10) c -= 10;
            seg[c * 128 + b] = tacc[k];
        }
    }
}

// ---------- reduce: grid 10, block 512 = 4 kseg x 128 b ----------
__global__ __launch_bounds__(512)
void reduce_k(const float* __restrict__ bias, float* __restrict__ out) {
    __shared__ float sm[512];
    const int c = blockIdx.x, t = threadIdx.x;
    const int b = t & 127, sg = t >> 7;
    const int NS = GRIDM * 2;                    // 280 slices
    float s = 0.f;
    for (int q = sg; q < NS; q += 4)
        s += g_part[q * (CC * 128) + c * 128 + b];
    sm[t] = s;
    __syncthreads();
    if (sg == 0)
        out[b * 10 + c] = sm[b] + sm[128 + b] + sm[256 + b] + sm[384 + b] + bias[c];
}

extern "C" void kernel_launch(void* const* d_in, const int* in_sizes, int n_in,
                              void* d_out, int out_size) {
    const float* X    = (const float*)d_in[0];
    const float* W    = (const float*)d_in[1];
    const float* bias = (const float*)d_in[2];
    float* out        = (float*)d_out;
    (void)in_sizes; (void)n_in; (void)out_size;

    cudaFuncSetAttribute(mma_main, cudaFuncAttributeMaxDynamicSharedMemorySize, SMEM_TOTAL);
    prep_a<<<208, 128>>>(X);
    mma_main<<<GRIDM, 256, SMEM_TOTAL>>>(X, W);
    reduce_k<<<CC, 512>>>(bias, out);
}

// round 11
// speedup vs baseline: 1.3551x; 1.0635x over previous
#include <cuda_runtime.h>
#include <cuda_bf16.h>
#include <cstdint>

#define DD    784
#define CC    10
#define NTOT  7840
#define NBC   112
#define GRIDM 140
#define NCHT  13
#define PITCH 144

#define TA_SZ   36864          // [2 split][128][72] bf16
#define OFF_TA0 0
#define OFF_TA1 36864
#define OFF_TB(i) (73728 + (i) * 36864)   // 3 buffers, each [2 split][128][72]
#define OFF_MBAR 184320
#define SMEM_TOTAL 184384
#define OFF_BNC 0              // bounce aliases TA after mainloop

__device__ __align__(16) unsigned char g_A[NCHT * TA_SZ];
__device__ float g_part[GRIDM * 2 * CC * 128];   // [slice][c][b]

__device__ __forceinline__ uint32_t smem_u32(const void* p) {
    uint32_t a;
    asm("{ .reg .u64 t; cvta.to.shared.u64 t, %1; cvt.u32.u64 %0, t; }" : "=r"(a) : "l"(p));
    return a;
}
#define MBAR_INIT(a, n) asm volatile("mbarrier.init.shared.b64 [%0], %1;" :: "r"(a), "r"(n) : "memory")
#define MBAR_EXPECT(a, n) asm volatile("mbarrier.arrive.expect_tx.shared.b64 _, [%0], %1;" :: "r"(a), "r"(n) : "memory")
#define MBAR_WAIT(a, ph) do {                                                   \
    asm volatile("{ .reg .pred P1; WL%=:"                                       \
        " mbarrier.try_wait.parity.acquire.cta.shared::cta.b64 P1, [%0], %1, 0x989680;" \
        " @P1 bra.uni WD%=; bra.uni WL%=; WD%=: }"                              \
        :: "r"(a), "r"(ph) : "memory");                                         \
} while (0)
#define BULK(dst, src, sz, mb) \
    asm volatile("cp.async.bulk.shared::cluster.global.mbarrier::complete_tx::bytes " \
        "[%0], [%1], %2, [%3];" :: "r"(dst), "l"(src), "r"(sz), "r"(mb) : "memory")
#define LDSM4(r, addr) \
    asm volatile("ldmatrix.sync.aligned.m8n8.x4.shared.b16 {%0,%1,%2,%3}, [%4];" \
        : "=r"((r)[0]), "=r"((r)[1]), "=r"((r)[2]), "=r"((r)[3]) : "r"(addr))
#define MMA_BF16(d, a, br0, br1) \
    asm volatile("mma.sync.aligned.m16n8k16.row.col.f32.bf16.bf16.f32 " \
        "{%0,%1,%2,%3}, {%4,%5,%6,%7}, {%8,%9}, {%0,%1,%2,%3};" \
        : "+f"((d)[0]), "+f"((d)[1]), "+f"((d)[2]), "+f"((d)[3]) \
        : "r"((a)[0]), "r"((a)[1]), "r"((a)[2]), "r"((a)[3]), "r"(br0), "r"(br1))

// ---------- prep: X -> bf16 hi/lo padded tile image per k-chunk ----------
__global__ __launch_bounds__(128)
void prep_a(const float* __restrict__ X) {
    int flat = blockIdx.x * 128 + threadIdx.x;   // 13*128*16 = 26624
    int ch  = flat >> 11;
    int rem = flat & 2047;
    int b   = rem >> 4;
    int k   = (rem & 15) * 4;
    int j   = ch * 64 + k;
    float f[4] = {0.f, 0.f, 0.f, 0.f};
    if (j < DD) {
        float4 v = *(const float4*)(X + b * DD + j);
        f[0] = v.x; f[1] = v.y; f[2] = v.z; f[3] = v.w;
    }
    __nv_bfloat16 h[4], l[4];
#pragma unroll
    for (int e = 0; e < 4; e++) {
        h[e] = __float2bfloat16(f[e]);
        l[e] = __float2bfloat16(f[e] - __bfloat162float(h[e]));
    }
    unsigned char* base = g_A + ch * TA_SZ + b * PITCH + k * 2;
    *(uint2*)(base)         = *(uint2*)h;
    *(uint2*)(base + 18432) = *(uint2*)l;
}

// ---------- main ----------
__global__ __launch_bounds__(256, 1)
void mma_main(const float* __restrict__ X, const float* __restrict__ W) {
    extern __shared__ __align__(16) unsigned char smem[];
    const uint32_t sb = smem_u32(smem);
    const int tid = threadIdx.x, lane = tid & 31, wid = tid >> 5;
    const int bx = blockIdx.x;
    const int nb_idx = bx >> 1, kb = bx & 1;
    const int n0 = nb_idx * NBC;
    const int NCH = 7;
    const int gch0 = kb ? 6 : 0;     // kb0: gch 0..6, kb1: gch 6..12

    const int wm = wid >> 1, wn = wid & 1;
    const int m_base = wm * 32, n_base = wn * 56;
    const int rsel = (lane & 7) + ((lane >> 3) & 1) * 8;
    const int k8b  = ((lane >> 4) * 8) * 2;
    int aoff[2], boff[4];
#pragma unroll
    for (int q = 0; q < 2; q++) aoff[q] = (m_base + q * 16 + rsel) * PITCH + k8b;
#pragma unroll
    for (int q = 0; q < 4; q++) boff[q] = (n_base + q * 16 + rsel) * PITCH + k8b;

    float acc[2][7][4];
#pragma unroll
    for (int a = 0; a < 2; a++)
#pragma unroll
        for (int t = 0; t < 7; t++)
#pragma unroll
            for (int e = 0; e < 4; e++) acc[a][t][e] = 0.f;

    // zero pad rows 112..127 of 3 TB buffers x 2 splits (6 x 576 words)
    for (int u = tid; u < 3456; u += 256) {
        int p = u / 576, off = u - p * 576;
        int base = OFF_TB(p >> 1) + (p & 1) * 18432 + 112 * PITCH;
        *(uint32_t*)(smem + base + off * 4) = 0;
    }
    if (tid == 0) { MBAR_INIT(sb + OFF_MBAR, 1); MBAR_INIT(sb + OFF_MBAR + 8, 1); }
    __syncthreads();

    auto issueA = [&](int ch) {
        if (tid == 0) {
            const int buf = ch & 1;
            const uint32_t mb = sb + OFF_MBAR + buf * 8;
            MBAR_EXPECT(mb, TA_SZ);
            BULK(sb + (buf ? OFF_TA1 : OFF_TA0), g_A + (gch0 + ch) * TA_SZ, TA_SZ, mb);
        }
    };

    // B plan: 224 active threads -> (n-pair np 0..55, k-quarter kq 0..3)
    // n = n0 + 2*np has even c, so (c, c+1) is contiguous & 8B aligned.
    const bool bact = tid < 224;
    const int np  = bact ? (tid % 56) : 0;
    const int kq  = bact ? (tid / 56) : 0;
    const int nl2 = 2 * np;                      // local n of pair base
    const int ng  = n0 + nl2;
    const int i_g = ng / 10;
    const int c_g = ng - i_g * 10;               // even
    const float* wbase = W + (size_t)(i_g + 1) * NTOT + c_g;

    float2 rB[16];
    auto loadB = [&](int ch) {
        if (!bact) return;
        const int j0 = (gch0 + ch) * 64 + kq * 16;
#pragma unroll
        for (int r = 0; r < 16; r++) {
            int j = j0 + r;
            rB[r] = (j < DD) ? *(const float2*)(wbase + (size_t)j * 10)
                             : make_float2(0.f, 0.f);
        }
    };
    auto storeB = [&](int tbuf) {
        if (!bact) return;
        unsigned char* tb = smem + OFF_TB(tbuf);
        const int kbyte = kq * 32;               // 16 k * 2B
#pragma unroll
        for (int m = 0; m < 8; m++) {
            float a0 = rB[2 * m].x, a1 = rB[2 * m + 1].x;   // row nl2
            float b0 = rB[2 * m].y, b1 = rB[2 * m + 1].y;   // row nl2+1
            __nv_bfloat162 ha, la, hb, lb;
            ha.x = __float2bfloat16(a0);  ha.y = __float2bfloat16(a1);
            la.x = __float2bfloat16(a0 - __bfloat162float(ha.x));
            la.y = __float2bfloat16(a1 - __bfloat162float(ha.y));
            hb.x = __float2bfloat16(b0);  hb.y = __float2bfloat16(b1);
            lb.x = __float2bfloat16(b0 - __bfloat162float(hb.x));
            lb.y = __float2bfloat16(b1 - __bfloat162float(hb.y));
            int o0 = nl2 * PITCH + kbyte + m * 4;
            int o1 = o0 + PITCH;
            *(__nv_bfloat162*)(tb + o0)         = ha;
            *(__nv_bfloat162*)(tb + 18432 + o0) = la;
            *(__nv_bfloat162*)(tb + o1)         = hb;
            *(__nv_bfloat162*)(tb + 18432 + o1) = lb;
        }
    };

    // prologue
    issueA(0); issueA(1);
    loadB(0);
    storeB(0);
    __syncthreads();
    loadB(1);

    for (int ch = 0; ch < NCH; ch++) {
        const int abuf = ch & 1;
        MBAR_WAIT(sb + OFF_MBAR + abuf * 8, (ch >> 1) & 1);

        // s-step range: balanced 25/24 split of the 49 real k16 steps
        int s_lo = 0, s_hi = 4;
        if (kb == 0) { if (ch == 6) s_hi = 1; }
        else         { if (ch == 0) s_lo = 1;  if (ch == 6) s_hi = 1; }

        const uint32_t tA = sb + (abuf ? OFF_TA1 : OFF_TA0);
        const uint32_t tB = sb + OFF_TB(ch % 3);
        for (int s = s_lo; s < s_hi; s++) {
            const int koff = s * 32;
            uint32_t ah[2][4], al[2][4], bb[4][4];
#pragma unroll
            for (int q = 0; q < 2; q++) {
                LDSM4(ah[q], tA + aoff[q] + koff);
                LDSM4(al[q], tA + 18432 + aoff[q] + koff);
            }
#pragma unroll
            for (int q = 0; q < 4; q++) LDSM4(bb[q], tB + boff[q] + koff);
#pragma unroll
            for (int mi = 0; mi < 2; mi++)
#pragma unroll
                for (int nt = 0; nt < 7; nt++) {
                    MMA_BF16(acc[mi][nt], ah[mi], bb[nt >> 1][nt & 1], bb[nt >> 1][(nt & 1) + 2]);
                    MMA_BF16(acc[mi][nt], al[mi], bb[nt >> 1][nt & 1], bb[nt >> 1][(nt & 1) + 2]);
                }
#pragma unroll
            for (int q = 0; q < 4; q++) LDSM4(bb[q], tB + 18432 + boff[q] + koff);
#pragma unroll
            for (int mi = 0; mi < 2; mi++)
#pragma unroll
                for (int nt = 0; nt < 7; nt++)
                    MMA_BF16(acc[mi][nt], ah[mi], bb[nt >> 1][nt & 1], bb[nt >> 1][(nt & 1) + 2]);
        }
        if (ch + 1 < NCH) storeB((ch + 1) % 3);  // overlaps MMA issue shadow
        __syncthreads();
        if (ch + 2 < NCH) { issueA(ch + 2); loadB(ch + 2); }
    }

    // ---- epilogue ----
    float* bnc = (float*)(smem + OFF_BNC);       // [128][114], aliases TA
    {
        const int r = lane >> 2, cq = (lane & 3) * 2;
#pragma unroll
        for (int mi = 0; mi < 2; mi++)
#pragma unroll
            for (int nt = 0; nt < 7; nt++) {
                int row = m_base + mi * 16 + r;
                int col = n_base + nt * 8 + cq;
                *(float2*)(bnc + row * 114 + col)       = make_float2(acc[mi][nt][0], acc[mi][nt][1]);
                *(float2*)(bnc + (row + 8) * 114 + col) = make_float2(acc[mi][nt][2], acc[mi][nt][3]);
            }
    }
    __syncthreads();
    {
        const int b = tid >> 1, half = tid & 1;
        const int nw = n0 + half * 56;
        const int i_b = nw / 10, r0 = nw - i_b * 10;
        float tacc[10];
#pragma unroll
        for (int k = 0; k < 10; k++) tacc[k] = 0.f;
#pragma unroll
        for (int nl = 0; nl < 56; nl++) {
            int idx = r0 + nl;
            int add = (idx >= 10) + (idx >= 20) + (idx >= 30) +
                      (idx >= 40) + (idx >= 50) + (idx >= 60);
            float xv = X[b * DD + i_b + add];
            float w1 = (kb == 0) ? W[nw + nl] : 0.f;
            float g  = bnc[b * 114 + half * 56 + nl];
            tacc[nl % 10] += xv * (g + w1);
        }
        float* seg = g_part + (bx * 2 + half) * (CC * 128);
#pragma unroll
        for (int k = 0; k < 10; k++) {
            int c = r0 + k; if (c >= 10) c -= 10;
            seg[c * 128 + b] = tacc[k];
        }
    }
}

// ---------- reduce: grid 10, block 1024 = 8 kseg x 128 b ----------
__global__ __launch_bounds__(1024)
void reduce_k(const float* __restrict__ bias, float* __restrict__ out) {
    __shared__ float sm[1024];
    const int c = blockIdx.x, t = threadIdx.x;
    const int b = t & 127, sg = t >> 7;
    const int NS = GRIDM * 2;                    // 280 slices
    float s = 0.f;
#pragma unroll 5
    for (int q = sg; q < NS; q += 8)
        s += g_part[q * (CC * 128) + c * 128 + b];
    sm[t] = s;
    __syncthreads();
    if (sg == 0) {
        float tot = bias[c];
#pragma unroll
        for (int k = 0; k < 8; k++) tot += sm[k * 128 + b];
        out[b * 10 + c] = tot;
    }
}

extern "C" void kernel_launch(void* const* d_in, const int* in_sizes, int n_in,
                              void* d_out, int out_size) {
    const float* X    = (const float*)d_in[0];
    const float* W    = (const float*)d_in[1];
    const float* bias = (const float*)d_in[2];
    float* out        = (float*)d_out;
    (void)in_sizes; (void)n_in; (void)out_size;

    cudaFuncSetAttribute(mma_main, cudaFuncAttributeMaxDynamicSharedMemorySize, SMEM_TOTAL);
    prep_a<<<208, 128>>>(X);
    mma_main<<<GRIDM, 256, SMEM_TOTAL>>>(X, W);
    reduce_k<<<CC, 1024>>>(bias, out);
}